// round 1
// baseline (speedup 1.0000x reference)
#include <cuda_runtime.h>
#include <math.h>

#define Bn      8
#define Nn      1024
#define DIMn    768
#define Hn      12
#define DHn     64
#define INNERn  768
#define NCn     2304          // 3 * INNER
#define Mrows   (Bn * Nn)     // 8192
#define SCALEf  0.125f        // DH^-0.5

// Scratch (allocation-free: __device__ globals)
__device__ float g_q[Bn * Hn * Nn * DHn];
__device__ float g_k[Bn * Hn * Nn * DHn];
__device__ float g_v[Bn * Hn * Nn * DHn];
__device__ float g_o[Mrows * INNERn];

// ---------------------------------------------------------------------------
// Tiled fp32 SGEMM: 128x128 tile, BK=16, 256 threads, 8x8 per thread.
// MODE 0: C = x @ w_qkv, scattered into g_q/g_k/g_v with head reshape.
// MODE 1: C = g_o @ w_out + b_out, written to d_out.
// ---------------------------------------------------------------------------
template <int MODE>
__global__ __launch_bounds__(256) void sgemm(const float* __restrict__ A,
                                             const float* __restrict__ Bm,
                                             float* __restrict__ C,
                                             const float* __restrict__ bias,
                                             int M, int Ncol, int K) {
    const int BK = 16;
    __shared__ float As[BK][132];   // padded pitch, A stored k-major
    __shared__ float Bs[BK][128];

    const int tid = threadIdx.x;
    const int bm0 = blockIdx.y * 128;
    const int bn0 = blockIdx.x * 128;
    const int ty = tid >> 4, tx = tid & 15;

    const float* Ap = (MODE == 1) ? g_o : A;

    float acc[8][8] = {};

    for (int k0 = 0; k0 < K; k0 += BK) {
        // Load A tile (2 float4 per thread), store transposed
#pragma unroll
        for (int l = 0; l < 2; l++) {
            int row = (tid >> 2) + l * 64;
            int col = (tid & 3) * 4;
            float4 v = *(const float4*)&Ap[(size_t)(bm0 + row) * K + k0 + col];
            As[col + 0][row] = v.x;
            As[col + 1][row] = v.y;
            As[col + 2][row] = v.z;
            As[col + 3][row] = v.w;
        }
        // Load B tile (2 float4 per thread)
#pragma unroll
        for (int l = 0; l < 2; l++) {
            int row = tid >> 4;
            int col = (tid & 15) * 4 + l * 64;
            *(float4*)&Bs[row][col] =
                *(const float4*)&Bm[(size_t)(k0 + row) * Ncol + bn0 + col];
        }
        __syncthreads();

#pragma unroll
        for (int k = 0; k < BK; k++) {
            float a[8], b[8];
            *(float4*)&a[0] = *(float4*)&As[k][ty * 8];
            *(float4*)&a[4] = *(float4*)&As[k][ty * 8 + 4];
            *(float4*)&b[0] = *(float4*)&Bs[k][tx * 8];
            *(float4*)&b[4] = *(float4*)&Bs[k][tx * 8 + 4];
#pragma unroll
            for (int r = 0; r < 8; r++)
#pragma unroll
                for (int c = 0; c < 8; c++)
                    acc[r][c] += a[r] * b[c];
        }
        __syncthreads();
    }

    if (MODE == 0) {
        // Scatter into q/k/v with [B,H,N,DH] layout
#pragma unroll
        for (int r = 0; r < 8; r++) {
            int m = bm0 + ty * 8 + r;
            int b = m >> 10;        // / N
            int i = m & 1023;       // % N
#pragma unroll
            for (int c = 0; c < 8; c++) {
                int n = bn0 + tx * 8 + c;
                int which = n / INNERn;
                int rem = n - which * INNERn;
                int h = rem >> 6;
                int d = rem & 63;
                float* dst = (which == 0) ? g_q : (which == 1) ? g_k : g_v;
                dst[(size_t)((b * Hn + h) * Nn + i) * DHn + d] = acc[r][c];
            }
        }
    } else {
#pragma unroll
        for (int r = 0; r < 8; r++) {
            int m = bm0 + ty * 8 + r;
#pragma unroll
            for (int c = 0; c < 8; c++) {
                int n = bn0 + tx * 8 + c;
                C[(size_t)m * Ncol + n] = acc[r][c] + bias[n];
            }
        }
    }
}

// ---------------------------------------------------------------------------
// Fused attention: one CTA = (b, h, 64 query rows). Flash-style online
// softmax over 16 KV tiles of 64. Q/K in smem d-major (conflict-free LDS.128).
// Relative-position bias row cached in smem; bias_idx computed analytically.
// Output written in [B, N, H*DH] layout so out-proj GEMM reads row-major.
// ---------------------------------------------------------------------------
__global__ __launch_bounds__(256) void attn_kernel(const float* __restrict__ bias_table) {
    extern __shared__ float sm[];
    float* Qs     = sm;            // [64][68]  d-major: Qs[d*68 + i]
    float* Ks     = sm + 4352;     // [64][68]  d-major: Ks[d*68 + j]
    float* Vs     = sm + 8704;     // [64][68]  j-major: Vs[j*68 + d]
    float* Ss     = sm + 13056;    // [64][68]  j-major: Ss[j*68 + i] (S/P transposed)
    float* bias_s = sm + 17408;    // [2048]
    float* row_l  = sm + 19456;    // [64]
    float* row_cr = sm + 19520;    // [64]
    // total 19584 floats = 78336 B

    const int tid = threadIdx.x;
    const int bh = blockIdx.y;
    const int b = bh / Hn, h = bh - b * Hn;
    const int q0 = blockIdx.x * 64;

    const float* qp = g_q + (size_t)bh * Nn * DHn;
    const float* kp = g_k + (size_t)bh * Nn * DHn;
    const float* vp = g_v + (size_t)bh * Nn * DHn;

    // Cache this head's bias row (2N-1 = 2047 entries)
    for (int t = tid; t < 2 * Nn - 1; t += 256)
        bias_s[t] = bias_table[h * (2 * Nn - 1) + t];

    // Load Q tile transposed (d-major)
#pragma unroll
    for (int l = 0; l < 4; l++) {
        int idx = tid + l * 256;
        int i = idx >> 4;
        int d = (idx & 15) * 4;
        float4 v = *(const float4*)&qp[(size_t)(q0 + i) * DHn + d];
        Qs[(d + 0) * 68 + i] = v.x;
        Qs[(d + 1) * 68 + i] = v.y;
        Qs[(d + 2) * 68 + i] = v.z;
        Qs[(d + 3) * 68 + i] = v.w;
    }

    const int ty = tid >> 4, tx = tid & 15;
    const int i0 = ty * 4;   // query rows (fixed across phases)
    const int x0 = tx * 4;   // S phase: j columns; PV phase: d columns

    float m_i = -1e30f, l_i = 0.f;  // online-softmax stats (valid for tid<64)
    float acc[4][4] = {};           // O accumulator: rows i0..i0+3, cols x0..x0+3

    for (int kv0 = 0; kv0 < Nn; kv0 += 64) {
        __syncthreads();  // protect Ks/Vs/Ss from previous iteration's readers

        // Load K transposed (d-major) and V direct (j-major)
#pragma unroll
        for (int l = 0; l < 4; l++) {
            int idx = tid + l * 256;
            int j = idx >> 4;
            int d = (idx & 15) * 4;
            float4 v = *(const float4*)&kp[(size_t)(kv0 + j) * DHn + d];
            Ks[(d + 0) * 68 + j] = v.x;
            Ks[(d + 1) * 68 + j] = v.y;
            Ks[(d + 2) * 68 + j] = v.z;
            Ks[(d + 3) * 68 + j] = v.w;
            *(float4*)&Vs[j * 68 + d] = *(const float4*)&vp[(size_t)(kv0 + j) * DHn + d];
        }
        __syncthreads();

        // S = Q @ K^T  (4x4 per thread, 2 LDS.128 per 16 FFMA)
        float s[4][4] = {};
#pragma unroll 8
        for (int d = 0; d < 64; d++) {
            float4 a = *(float4*)&Qs[d * 68 + i0];
            float4 bb = *(float4*)&Ks[d * 68 + x0];
            float av[4] = {a.x, a.y, a.z, a.w};
            float bv[4] = {bb.x, bb.y, bb.z, bb.w};
#pragma unroll
            for (int r = 0; r < 4; r++)
#pragma unroll
                for (int c = 0; c < 4; c++)
                    s[r][c] += av[r] * bv[c];
        }

        // scale + relative-position bias, store S transposed (j-major)
#pragma unroll
        for (int r = 0; r < 4; r++) {
            int gi = q0 + i0 + r;
#pragma unroll
            for (int c = 0; c < 4; c++) {
                int gj = kv0 + x0 + c;
                int off = gi - gj;
                int idx = (off <= 0) ? -off : (Nn - 1 + off);
                Ss[(x0 + c) * 68 + (i0 + r)] = s[r][c] * SCALEf + bias_s[idx];
            }
        }
        __syncthreads();

        // Online softmax: threads 0..63 each own one query row
        if (tid < 64) {
            float mx = m_i;
#pragma unroll 8
            for (int j = 0; j < 64; j++) mx = fmaxf(mx, Ss[j * 68 + tid]);
            float corr = __expf(m_i - mx);
            float l = l_i * corr;
#pragma unroll 8
            for (int j = 0; j < 64; j++) {
                float p = __expf(Ss[j * 68 + tid] - mx);
                Ss[j * 68 + tid] = p;
                l += p;
            }
            m_i = mx;
            l_i = l;
            row_cr[tid] = corr;
        }
        __syncthreads();

        // Rescale accumulator and add P @ V
        float cr[4];
#pragma unroll
        for (int r = 0; r < 4; r++) cr[r] = row_cr[i0 + r];
#pragma unroll
        for (int r = 0; r < 4; r++)
#pragma unroll
            for (int c = 0; c < 4; c++)
                acc[r][c] *= cr[r];

#pragma unroll 8
        for (int j = 0; j < 64; j++) {
            float4 p = *(float4*)&Ss[j * 68 + i0];
            float4 vv = *(float4*)&Vs[j * 68 + x0];
            float pv[4] = {p.x, p.y, p.z, p.w};
            float vf[4] = {vv.x, vv.y, vv.z, vv.w};
#pragma unroll
            for (int r = 0; r < 4; r++)
#pragma unroll
                for (int c = 0; c < 4; c++)
                    acc[r][c] += pv[r] * vf[c];
        }
    }

    __syncthreads();
    if (tid < 64) row_l[tid] = l_i;
    __syncthreads();

    // Normalize and write O in [B, N, H*DH] layout
#pragma unroll
    for (int r = 0; r < 4; r++) {
        float inv = 1.f / row_l[i0 + r];
        int gi = q0 + i0 + r;
        float4 o;
        o.x = acc[r][0] * inv;
        o.y = acc[r][1] * inv;
        o.z = acc[r][2] * inv;
        o.w = acc[r][3] * inv;
        *(float4*)&g_o[(size_t)(b * Nn + gi) * INNERn + h * DHn + x0] = o;
    }
}

// ---------------------------------------------------------------------------
extern "C" void kernel_launch(void* const* d_in, const int* in_sizes, int n_in,
                              void* d_out, int out_size) {
    const float* x          = (const float*)d_in[0];
    const float* w_qkv      = (const float*)d_in[1];
    const float* bias_table = (const float*)d_in[2];
    const float* w_out      = (const float*)d_in[3];
    const float* b_out      = (const float*)d_in[4];
    // d_in[5] = bias_idx (int32) — computed analytically in-kernel
    float* out = (float*)d_out;

    const int ATTN_SMEM = 19584 * (int)sizeof(float);  // 78336 B
    cudaFuncSetAttribute(attn_kernel, cudaFuncAttributeMaxDynamicSharedMemorySize,
                         ATTN_SMEM);

    // 1) QKV projection + head reshape
    dim3 g1(NCn / 128, Mrows / 128);
    sgemm<0><<<g1, 256>>>(x, w_qkv, nullptr, nullptr, Mrows, NCn, DIMn);

    // 2) Fused attention with relative-position bias
    dim3 g2(Nn / 64, Bn * Hn);
    attn_kernel<<<g2, 256, ATTN_SMEM>>>(bias_table);

    // 3) Output projection + bias
    dim3 g3(INNERn / 128, Mrows / 128);
    sgemm<1><<<g3, 256>>>(nullptr, w_out, out, b_out, Mrows, INNERn, INNERn);
}

// round 3
// speedup vs baseline: 1.4324x; 1.4324x over previous
#include <cuda_runtime.h>
#include <cuda_bf16.h>
#include <cstdint>
#include <math.h>

#define Bn      8
#define Nn      1024
#define DIMn    768
#define Hn      12
#define DHn     64
#define INNERn  768
#define NCn     2304
#define Mrows   (Bn * Nn)     // 8192
#define SCALEf  0.125f

// ---------------------------------------------------------------------------
// Scratch (allocation-free __device__ globals)
// ---------------------------------------------------------------------------
__device__ float g_q[Bn * Hn * Nn * DHn];
__device__ float g_k[Bn * Hn * Nn * DHn];
__device__ float g_v[Bn * Hn * Nn * DHn];
__device__ __nv_bfloat16 g_xh[Mrows * DIMn];
__device__ __nv_bfloat16 g_xl[Mrows * DIMn];
__device__ __nv_bfloat16 g_wqh[NCn * DIMn];     // w_qkv transposed [N][K]
__device__ __nv_bfloat16 g_wql[NCn * DIMn];
__device__ __nv_bfloat16 g_woh[INNERn * DIMn];  // w_out transposed [N][K]
__device__ __nv_bfloat16 g_wol[INNERn * DIMn];
__device__ __nv_bfloat16 g_oh[Mrows * INNERn];
__device__ __nv_bfloat16 g_ol[Mrows * INNERn];

// ---------------------------------------------------------------------------
// Helpers
// ---------------------------------------------------------------------------
__device__ __forceinline__ uint32_t smem_u32(const void* p) {
    uint32_t a;
    asm("{ .reg .u64 t; cvta.to.shared.u64 t, %1; cvt.u32.u64 %0, t; }"
        : "=r"(a) : "l"(p));
    return a;
}

__device__ __forceinline__ void cp16(uint32_t s, const void* g) {
    asm volatile("cp.async.cg.shared.global [%0], [%1], 16;" :: "r"(s), "l"(g));
}
#define CP_COMMIT() asm volatile("cp.async.commit_group;" ::: "memory")
#define CP_WAIT(N)  asm volatile("cp.async.wait_group %0;" :: "n"(N) : "memory")

__device__ __forceinline__ void mma16816(float* d, const uint32_t* a,
                                         uint32_t b0, uint32_t b1) {
    asm volatile(
        "mma.sync.aligned.m16n8k16.row.col.f32.bf16.bf16.f32 "
        "{%0,%1,%2,%3}, {%4,%5,%6,%7}, {%8,%9}, {%0,%1,%2,%3};"
        : "+f"(d[0]), "+f"(d[1]), "+f"(d[2]), "+f"(d[3])
        : "r"(a[0]), "r"(a[1]), "r"(a[2]), "r"(a[3]), "r"(b0), "r"(b1));
}

__device__ __forceinline__ uint32_t pack_bf16x2(float a, float b) {
    __nv_bfloat162 t = __floats2bfloat162_rn(a, b);
    return *reinterpret_cast<uint32_t*>(&t);
}

// ---------------------------------------------------------------------------
// Split fp32 -> bf16 hi/lo (vectorized)
// ---------------------------------------------------------------------------
__global__ void split_f32(const float* __restrict__ s,
                          __nv_bfloat16* __restrict__ hi,
                          __nv_bfloat16* __restrict__ lo, int n4) {
    int i = blockIdx.x * blockDim.x + threadIdx.x;
    if (i >= n4) return;
    float4 v = reinterpret_cast<const float4*>(s)[i];
    __nv_bfloat16 h0 = __float2bfloat16(v.x);
    __nv_bfloat16 h1 = __float2bfloat16(v.y);
    __nv_bfloat16 h2 = __float2bfloat16(v.z);
    __nv_bfloat16 h3 = __float2bfloat16(v.w);
    uint2 hp, lp;
    hp.x = pack_bf16x2(__bfloat162float(h0), __bfloat162float(h1));
    hp.y = pack_bf16x2(__bfloat162float(h2), __bfloat162float(h3));
    // re-pack using exact rounded bits
    {
        __nv_bfloat162 t01, t23;
        t01.x = h0; t01.y = h1; t23.x = h2; t23.y = h3;
        hp.x = *reinterpret_cast<uint32_t*>(&t01);
        hp.y = *reinterpret_cast<uint32_t*>(&t23);
    }
    lp.x = pack_bf16x2(v.x - __bfloat162float(h0), v.y - __bfloat162float(h1));
    lp.y = pack_bf16x2(v.z - __bfloat162float(h2), v.w - __bfloat162float(h3));
    reinterpret_cast<uint2*>(hi)[i] = hp;
    reinterpret_cast<uint2*>(lo)[i] = lp;
}

// ---------------------------------------------------------------------------
// Transpose + split: src [K][N] fp32  ->  dh/dl [N][K] bf16
// ---------------------------------------------------------------------------
__global__ __launch_bounds__(256) void splitT(const float* __restrict__ src,
                                              __nv_bfloat16* __restrict__ dh,
                                              __nv_bfloat16* __restrict__ dl,
                                              int K, int N) {
    __shared__ float t[32][33];
    const int k0 = blockIdx.y * 32, n0 = blockIdx.x * 32;
    const int tx = threadIdx.x & 31, ty = threadIdx.x >> 5;  // ty 0..7
#pragma unroll
    for (int i = 0; i < 32; i += 8)
        t[ty + i][tx] = src[(size_t)(k0 + ty + i) * N + n0 + tx];
    __syncthreads();
#pragma unroll
    for (int i = 0; i < 32; i += 8) {
        float v = t[tx][ty + i];  // element (k=k0+tx, n=n0+ty+i)
        __nv_bfloat16 h = __float2bfloat16(v);
        size_t idx = (size_t)(n0 + ty + i) * K + k0 + tx;
        dh[idx] = h;
        dl[idx] = __float2bfloat16(v - __bfloat162float(h));
    }
}

// ---------------------------------------------------------------------------
// bf16x3 GEMM via mma.sync: C[M, Ncol] = A[M,768] @ B^T  (B stored [Ncol][768])
// CTA 128x128, BK=32, 8 warps (4x2), double-buffered cp.async.
// MODE 0: scatter into g_q/g_k/g_v (head reshape). MODE 1: C = .. + bias.
// ---------------------------------------------------------------------------
#define PITCH 80                        // bytes per 32-bf16 row (40 bf16)
#define TILE_B (128 * PITCH)            // 10240 B per tile
#define BUF_B (4 * TILE_B)              // Ah, Al, Bh, Bl
#define GEMM_SMEM (2 * BUF_B)           // 81920 B

template <int MODE>
__global__ __launch_bounds__(256) void mma_gemm(
    const __nv_bfloat16* __restrict__ Ah, const __nv_bfloat16* __restrict__ Al,
    const __nv_bfloat16* __restrict__ Bh, const __nv_bfloat16* __restrict__ Bl,
    float* __restrict__ C, const float* __restrict__ bias, int Ncol) {
    extern __shared__ char sm[];
    const int tid = threadIdx.x;
    const int wid = tid >> 5;
    const int lane = tid & 31;
    const int wr = wid >> 1;   // 0..3  (M)
    const int wc = wid & 1;    // 0..1  (N)

    const int bm0 = blockIdx.y * 128;
    const int bn0 = blockIdx.x * 128;
    const uint32_t sb = smem_u32(sm);

    float acc[2][8][4] = {};

    // ---- tile loader: 4 tiles, 2048 16B-chunks, 8 per thread ----
    auto load_tiles = [&](int it, int buf) {
        const int k0 = it * 32;
        const uint32_t base = sb + buf * BUF_B;
#pragma unroll
        for (int i = 0; i < 2; i++) {
            const int idx = tid + i * 256;
            const int row = idx >> 2;
            const int ch = idx & 3;
            const uint32_t so = row * PITCH + ch * 16;
            const size_t gA = (size_t)(bm0 + row) * DIMn + k0 + ch * 8;
            const size_t gB = (size_t)(bn0 + row) * DIMn + k0 + ch * 8;
            cp16(base + so, Ah + gA);
            cp16(base + TILE_B + so, Al + gA);
            cp16(base + 2 * TILE_B + so, Bh + gB);
            cp16(base + 3 * TILE_B + so, Bl + gB);
        }
    };

    load_tiles(0, 0);
    CP_COMMIT();

    const int nIter = DIMn / 32;  // 24
    for (int it = 0; it < nIter; ++it) {
        if (it + 1 < nIter) {
            load_tiles(it + 1, (it + 1) & 1);
            CP_COMMIT();
            CP_WAIT(1);
        } else {
            CP_WAIT(0);
        }
        __syncthreads();

        const char* base = sm + (it & 1) * BUF_B;
        const char* ahp = base;
        const char* alp = base + TILE_B;
        const char* bhp = base + 2 * TILE_B;
        const char* blp = base + 3 * TILE_B;

#pragma unroll
        for (int k16 = 0; k16 < 32; k16 += 16) {
            // A fragments (hi and lo) for 2 m-tiles
            uint32_t ah[2][4], al[2][4];
            const int arow = wr * 32 + (lane >> 2);
            const int acol = (k16 + (lane & 3) * 2) * 2;  // byte offset in row
#pragma unroll
            for (int mt = 0; mt < 2; mt++) {
                const int r0 = (arow + mt * 16) * PITCH + acol;
                const int r1 = r0 + 8 * PITCH;
                ah[mt][0] = *(const uint32_t*)(ahp + r0);
                ah[mt][1] = *(const uint32_t*)(ahp + r1);
                ah[mt][2] = *(const uint32_t*)(ahp + r0 + 16);
                ah[mt][3] = *(const uint32_t*)(ahp + r1 + 16);
                al[mt][0] = *(const uint32_t*)(alp + r0);
                al[mt][1] = *(const uint32_t*)(alp + r1);
                al[mt][2] = *(const uint32_t*)(alp + r0 + 16);
                al[mt][3] = *(const uint32_t*)(alp + r1 + 16);
            }
#pragma unroll
            for (int nt = 0; nt < 8; nt++) {
                const int brow = wc * 64 + nt * 8 + (lane >> 2);
                const int bo = brow * PITCH + acol;
                const uint32_t bh0 = *(const uint32_t*)(bhp + bo);
                const uint32_t bh1 = *(const uint32_t*)(bhp + bo + 16);
                const uint32_t bl0 = *(const uint32_t*)(blp + bo);
                const uint32_t bl1 = *(const uint32_t*)(blp + bo + 16);
#pragma unroll
                for (int mt = 0; mt < 2; mt++) {
                    mma16816(acc[mt][nt], ah[mt], bh0, bh1);
                    mma16816(acc[mt][nt], al[mt], bh0, bh1);
                    mma16816(acc[mt][nt], ah[mt], bl0, bl1);
                }
            }
        }
        __syncthreads();
    }

    // ---- epilogue ----
#pragma unroll
    for (int mt = 0; mt < 2; mt++) {
        const int ra = bm0 + wr * 32 + mt * 16 + (lane >> 2);
        const int rb = ra + 8;
#pragma unroll
        for (int nt = 0; nt < 8; nt++) {
            const int n = bn0 + wc * 64 + nt * 8 + (lane & 3) * 2;
            if (MODE == 0) {
                const int which = n / INNERn;
                const int rem = n - which * INNERn;
                const int h = rem >> 6;
                const int d = rem & 63;
                float* dst = (which == 0) ? g_q : (which == 1) ? g_k : g_v;
                {
                    const int b = ra >> 10, i = ra & 1023;
                    float2 v = {acc[mt][nt][0], acc[mt][nt][1]};
                    *(float2*)&dst[(size_t)((b * Hn + h) * Nn + i) * DHn + d] = v;
                }
                {
                    const int b = rb >> 10, i = rb & 1023;
                    float2 v = {acc[mt][nt][2], acc[mt][nt][3]};
                    *(float2*)&dst[(size_t)((b * Hn + h) * Nn + i) * DHn + d] = v;
                }
            } else {
                const float b0 = bias[n], b1 = bias[n + 1];
                float2 v0 = {acc[mt][nt][0] + b0, acc[mt][nt][1] + b1};
                float2 v1 = {acc[mt][nt][2] + b0, acc[mt][nt][3] + b1};
                *(float2*)&C[(size_t)ra * Ncol + n] = v0;
                *(float2*)&C[(size_t)rb * Ncol + n] = v1;
            }
        }
    }
}

// ---------------------------------------------------------------------------
// Fused attention (fp32 FFMA, flash-style) — writes O as bf16 hi/lo split
// ---------------------------------------------------------------------------
__global__ __launch_bounds__(256) void attn_kernel(const float* __restrict__ bias_table) {
    extern __shared__ float smf[];
    float* Qs     = smf;
    float* Ks     = smf + 4352;
    float* Vs     = smf + 8704;
    float* Ss     = smf + 13056;
    float* bias_s = smf + 17408;
    float* row_l  = smf + 19456;
    float* row_cr = smf + 19520;

    const int tid = threadIdx.x;
    const int bh = blockIdx.y;
    const int b = bh / Hn, h = bh - b * Hn;
    const int q0 = blockIdx.x * 64;

    const float* qp = g_q + (size_t)bh * Nn * DHn;
    const float* kp = g_k + (size_t)bh * Nn * DHn;
    const float* vp = g_v + (size_t)bh * Nn * DHn;

    for (int t = tid; t < 2 * Nn - 1; t += 256)
        bias_s[t] = bias_table[h * (2 * Nn - 1) + t];

#pragma unroll
    for (int l = 0; l < 4; l++) {
        int idx = tid + l * 256;
        int i = idx >> 4;
        int d = (idx & 15) * 4;
        float4 v = *(const float4*)&qp[(size_t)(q0 + i) * DHn + d];
        Qs[(d + 0) * 68 + i] = v.x;
        Qs[(d + 1) * 68 + i] = v.y;
        Qs[(d + 2) * 68 + i] = v.z;
        Qs[(d + 3) * 68 + i] = v.w;
    }

    const int ty = tid >> 4, tx = tid & 15;
    const int i0 = ty * 4;
    const int x0 = tx * 4;

    float m_i = -1e30f, l_i = 0.f;
    float acc[4][4] = {};

    for (int kv0 = 0; kv0 < Nn; kv0 += 64) {
        __syncthreads();

#pragma unroll
        for (int l = 0; l < 4; l++) {
            int idx = tid + l * 256;
            int j = idx >> 4;
            int d = (idx & 15) * 4;
            float4 v = *(const float4*)&kp[(size_t)(kv0 + j) * DHn + d];
            Ks[(d + 0) * 68 + j] = v.x;
            Ks[(d + 1) * 68 + j] = v.y;
            Ks[(d + 2) * 68 + j] = v.z;
            Ks[(d + 3) * 68 + j] = v.w;
            *(float4*)&Vs[j * 68 + d] = *(const float4*)&vp[(size_t)(kv0 + j) * DHn + d];
        }
        __syncthreads();

        float s[4][4] = {};
#pragma unroll 8
        for (int d = 0; d < 64; d++) {
            float4 a = *(float4*)&Qs[d * 68 + i0];
            float4 bb = *(float4*)&Ks[d * 68 + x0];
            float av[4] = {a.x, a.y, a.z, a.w};
            float bv[4] = {bb.x, bb.y, bb.z, bb.w};
#pragma unroll
            for (int r = 0; r < 4; r++)
#pragma unroll
                for (int c = 0; c < 4; c++)
                    s[r][c] += av[r] * bv[c];
        }

#pragma unroll
        for (int r = 0; r < 4; r++) {
            int gi = q0 + i0 + r;
#pragma unroll
            for (int c = 0; c < 4; c++) {
                int gj = kv0 + x0 + c;
                int off = gi - gj;
                int idx = (off <= 0) ? -off : (Nn - 1 + off);
                Ss[(x0 + c) * 68 + (i0 + r)] = s[r][c] * SCALEf + bias_s[idx];
            }
        }
        __syncthreads();

        if (tid < 64) {
            float mx = m_i;
#pragma unroll 8
            for (int j = 0; j < 64; j++) mx = fmaxf(mx, Ss[j * 68 + tid]);
            float corr = __expf(m_i - mx);
            float l = l_i * corr;
#pragma unroll 8
            for (int j = 0; j < 64; j++) {
                float p = __expf(Ss[j * 68 + tid] - mx);
                Ss[j * 68 + tid] = p;
                l += p;
            }
            m_i = mx;
            l_i = l;
            row_cr[tid] = corr;
        }
        __syncthreads();

        float cr[4];
#pragma unroll
        for (int r = 0; r < 4; r++) cr[r] = row_cr[i0 + r];
#pragma unroll
        for (int r = 0; r < 4; r++)
#pragma unroll
            for (int c = 0; c < 4; c++)
                acc[r][c] *= cr[r];

#pragma unroll 8
        for (int j = 0; j < 64; j++) {
            float4 p = *(float4*)&Ss[j * 68 + i0];
            float4 vv = *(float4*)&Vs[j * 68 + x0];
            float pv[4] = {p.x, p.y, p.z, p.w};
            float vf[4] = {vv.x, vv.y, vv.z, vv.w};
#pragma unroll
            for (int r = 0; r < 4; r++)
#pragma unroll
                for (int c = 0; c < 4; c++)
                    acc[r][c] += pv[r] * vf[c];
        }
    }

    __syncthreads();
    if (tid < 64) row_l[tid] = l_i;
    __syncthreads();

#pragma unroll
    for (int r = 0; r < 4; r++) {
        float inv = 1.f / row_l[i0 + r];
        int gi = q0 + i0 + r;
        float o[4];
#pragma unroll
        for (int c = 0; c < 4; c++) o[c] = acc[r][c] * inv;
        size_t idx = (size_t)(b * Nn + gi) * INNERn + h * DHn + x0;
        __nv_bfloat16 h0 = __float2bfloat16(o[0]);
        __nv_bfloat16 h1 = __float2bfloat16(o[1]);
        __nv_bfloat16 h2 = __float2bfloat16(o[2]);
        __nv_bfloat16 h3 = __float2bfloat16(o[3]);
        uint2 hp, lp;
        {
            __nv_bfloat162 t01, t23;
            t01.x = h0; t01.y = h1; t23.x = h2; t23.y = h3;
            hp.x = *reinterpret_cast<uint32_t*>(&t01);
            hp.y = *reinterpret_cast<uint32_t*>(&t23);
        }
        lp.x = pack_bf16x2(o[0] - __bfloat162float(h0), o[1] - __bfloat162float(h1));
        lp.y = pack_bf16x2(o[2] - __bfloat162float(h2), o[3] - __bfloat162float(h3));
        *reinterpret_cast<uint2*>(&g_oh[idx]) = hp;
        *reinterpret_cast<uint2*>(&g_ol[idx]) = lp;
    }
}

// ---------------------------------------------------------------------------
extern "C" void kernel_launch(void* const* d_in, const int* in_sizes, int n_in,
                              void* d_out, int out_size) {
    const float* x          = (const float*)d_in[0];
    const float* w_qkv      = (const float*)d_in[1];
    const float* bias_table = (const float*)d_in[2];
    const float* w_out      = (const float*)d_in[3];
    const float* b_out      = (const float*)d_in[4];
    float* out = (float*)d_out;

    const int ATTN_SMEM = 19584 * (int)sizeof(float);
    cudaFuncSetAttribute(attn_kernel, cudaFuncAttributeMaxDynamicSharedMemorySize,
                         ATTN_SMEM);
    cudaFuncSetAttribute(mma_gemm<0>, cudaFuncAttributeMaxDynamicSharedMemorySize,
                         GEMM_SMEM);
    cudaFuncSetAttribute(mma_gemm<1>, cudaFuncAttributeMaxDynamicSharedMemorySize,
                         GEMM_SMEM);

    __nv_bfloat16 *xh, *xl, *wqh, *wql, *woh, *wol, *oh, *ol;
    cudaGetSymbolAddress((void**)&xh, g_xh);
    cudaGetSymbolAddress((void**)&xl, g_xl);
    cudaGetSymbolAddress((void**)&wqh, g_wqh);
    cudaGetSymbolAddress((void**)&wql, g_wql);
    cudaGetSymbolAddress((void**)&woh, g_woh);
    cudaGetSymbolAddress((void**)&wol, g_wol);
    cudaGetSymbolAddress((void**)&oh, g_oh);
    cudaGetSymbolAddress((void**)&ol, g_ol);

    // 0) splits (x, w_qkv^T, w_out^T)
    split_f32<<<(Mrows * DIMn / 4 + 255) / 256, 256>>>(x, xh, xl, Mrows * DIMn / 4);
    splitT<<<dim3(NCn / 32, DIMn / 32), 256>>>(w_qkv, wqh, wql, DIMn, NCn);
    splitT<<<dim3(INNERn / 32, DIMn / 32), 256>>>(w_out, woh, wol, DIMn, INNERn);

    // 1) QKV projection (bf16x3 mma.sync) + head reshape
    dim3 g1(NCn / 128, Mrows / 128);
    mma_gemm<0><<<g1, 256, GEMM_SMEM>>>(xh, xl, wqh, wql, nullptr, nullptr, NCn);

    // 2) Fused attention (fp32), emits O split (bf16 hi/lo)
    dim3 g2(Nn / 64, Bn * Hn);
    attn_kernel<<<g2, 256, ATTN_SMEM>>>(bias_table);

    // 3) Output projection (bf16x3 mma.sync) + bias
    dim3 g3(INNERn / 128, Mrows / 128);
    mma_gemm<1><<<g3, 256, GEMM_SMEM>>>(oh, ol, woh, wol, out, b_out, INNERn);
}

// round 4
// speedup vs baseline: 2.9407x; 2.0530x over previous
#include <cuda_runtime.h>
#include <cuda_bf16.h>
#include <cstdint>
#include <math.h>

#define Bn      8
#define Nn      1024
#define DIMn    768
#define Hn      12
#define DHn     64
#define INNERn  768
#define NCn     2304
#define Mrows   (Bn * Nn)     // 8192
#define SCALEf  0.125f

// ---------------------------------------------------------------------------
// Scratch (allocation-free __device__ globals)
// ---------------------------------------------------------------------------
__device__ __nv_bfloat16 g_qh[Bn * Hn * Nn * DHn];  // [bh][i][d], pre-scaled
__device__ __nv_bfloat16 g_ql[Bn * Hn * Nn * DHn];
__device__ __nv_bfloat16 g_kh[Bn * Hn * Nn * DHn];  // [bh][j][d]
__device__ __nv_bfloat16 g_kl[Bn * Hn * Nn * DHn];
__device__ __nv_bfloat16 g_vth[Bn * Hn * DHn * Nn]; // [bh][d][j]  (transposed)
__device__ __nv_bfloat16 g_vtl[Bn * Hn * DHn * Nn];
__device__ __nv_bfloat16 g_xh[Mrows * DIMn];
__device__ __nv_bfloat16 g_xl[Mrows * DIMn];
__device__ __nv_bfloat16 g_wqh[NCn * DIMn];     // w_qkv transposed [N][K]
__device__ __nv_bfloat16 g_wql[NCn * DIMn];
__device__ __nv_bfloat16 g_woh[INNERn * DIMn];  // w_out transposed [N][K]
__device__ __nv_bfloat16 g_wol[INNERn * DIMn];
__device__ __nv_bfloat16 g_oh[Mrows * INNERn];
__device__ __nv_bfloat16 g_ol[Mrows * INNERn];

// ---------------------------------------------------------------------------
// Helpers
// ---------------------------------------------------------------------------
__device__ __forceinline__ uint32_t smem_u32(const void* p) {
    uint32_t a;
    asm("{ .reg .u64 t; cvta.to.shared.u64 t, %1; cvt.u32.u64 %0, t; }"
        : "=r"(a) : "l"(p));
    return a;
}

__device__ __forceinline__ void cp16(uint32_t s, const void* g) {
    asm volatile("cp.async.cg.shared.global [%0], [%1], 16;" :: "r"(s), "l"(g));
}
#define CP_COMMIT() asm volatile("cp.async.commit_group;" ::: "memory")
#define CP_WAIT(N)  asm volatile("cp.async.wait_group %0;" :: "n"(N) : "memory")

__device__ __forceinline__ uint32_t lds32(uint32_t a) {
    uint32_t v;
    asm volatile("ld.shared.b32 %0, [%1];" : "=r"(v) : "r"(a));
    return v;
}

__device__ __forceinline__ void mma16816(float* d, const uint32_t* a,
                                         uint32_t b0, uint32_t b1) {
    asm volatile(
        "mma.sync.aligned.m16n8k16.row.col.f32.bf16.bf16.f32 "
        "{%0,%1,%2,%3}, {%4,%5,%6,%7}, {%8,%9}, {%0,%1,%2,%3};"
        : "+f"(d[0]), "+f"(d[1]), "+f"(d[2]), "+f"(d[3])
        : "r"(a[0]), "r"(a[1]), "r"(a[2]), "r"(a[3]), "r"(b0), "r"(b1));
}

__device__ __forceinline__ uint32_t pack_bf16x2(float a, float b) {
    __nv_bfloat162 t = __floats2bfloat162_rn(a, b);
    return *reinterpret_cast<uint32_t*>(&t);
}

// hi/lo split of a float pair into two packed bf16x2
__device__ __forceinline__ void split_pair(float a, float b, uint32_t& hi, uint32_t& lo) {
    __nv_bfloat16 ha = __float2bfloat16(a);
    __nv_bfloat16 hb = __float2bfloat16(b);
    __nv_bfloat162 t; t.x = ha; t.y = hb;
    hi = *reinterpret_cast<uint32_t*>(&t);
    lo = pack_bf16x2(a - __bfloat162float(ha), b - __bfloat162float(hb));
}

// XOR swizzle within a 128B row of bf16 (16B chunk granularity)
__device__ __forceinline__ uint32_t swz(int row, int cbyte) {
    return (uint32_t)(row * 128 + ((((cbyte >> 4) ^ row) & 7) << 4) + (cbyte & 15)
                      + (cbyte & ~0x7F));
}
// NOTE: cbyte < 128 always in our usage; keep it simple:
__device__ __forceinline__ uint32_t swz128(int row, int cbyte) {
    return (uint32_t)(row * 128 + (((cbyte >> 4) ^ (row & 7)) << 4) + (cbyte & 15));
}

// ---------------------------------------------------------------------------
// Split fp32 -> bf16 hi/lo (vectorized)
// ---------------------------------------------------------------------------
__global__ void split_f32(const float* __restrict__ s,
                          __nv_bfloat16* __restrict__ hi,
                          __nv_bfloat16* __restrict__ lo, int n4) {
    int i = blockIdx.x * blockDim.x + threadIdx.x;
    if (i >= n4) return;
    float4 v = reinterpret_cast<const float4*>(s)[i];
    uint2 hp, lp;
    split_pair(v.x, v.y, hp.x, lp.x);
    split_pair(v.z, v.w, hp.y, lp.y);
    reinterpret_cast<uint2*>(hi)[i] = hp;
    reinterpret_cast<uint2*>(lo)[i] = lp;
}

// ---------------------------------------------------------------------------
// Transpose + split: src [K][N] fp32  ->  dh/dl [N][K] bf16
// ---------------------------------------------------------------------------
__global__ __launch_bounds__(256) void splitT(const float* __restrict__ src,
                                              __nv_bfloat16* __restrict__ dh,
                                              __nv_bfloat16* __restrict__ dl,
                                              int K, int N) {
    __shared__ float t[32][33];
    const int k0 = blockIdx.y * 32, n0 = blockIdx.x * 32;
    const int tx = threadIdx.x & 31, ty = threadIdx.x >> 5;
#pragma unroll
    for (int i = 0; i < 32; i += 8)
        t[ty + i][tx] = src[(size_t)(k0 + ty + i) * N + n0 + tx];
    __syncthreads();
#pragma unroll
    for (int i = 0; i < 32; i += 8) {
        float v = t[tx][ty + i];
        __nv_bfloat16 h = __float2bfloat16(v);
        size_t idx = (size_t)(n0 + ty + i) * K + k0 + tx;
        dh[idx] = h;
        dl[idx] = __float2bfloat16(v - __bfloat162float(h));
    }
}

// ---------------------------------------------------------------------------
// bf16x3 GEMM via mma.sync: C[M, Ncol] = A[M,768] @ B^T  (B stored [Ncol][768])
// CTA 128x128, BK=32, 8 warps (4x2), double-buffered cp.async.
// MODE 0: emit q/k (bf16 hi/lo, q pre-scaled) and v transposed.
// MODE 1: C = .. + bias (fp32 to d_out).
// ---------------------------------------------------------------------------
#define PITCH 80
#define TILE_B (128 * PITCH)
#define BUF_B (4 * TILE_B)
#define GEMM_SMEM (2 * BUF_B)

template <int MODE>
__global__ __launch_bounds__(256) void mma_gemm(
    const __nv_bfloat16* __restrict__ Ah, const __nv_bfloat16* __restrict__ Al,
    const __nv_bfloat16* __restrict__ Bh, const __nv_bfloat16* __restrict__ Bl,
    float* __restrict__ C, const float* __restrict__ bias, int Ncol) {
    extern __shared__ char sm[];
    const int tid = threadIdx.x;
    const int wid = tid >> 5;
    const int lane = tid & 31;
    const int wr = wid >> 1;
    const int wc = wid & 1;

    const int bm0 = blockIdx.y * 128;
    const int bn0 = blockIdx.x * 128;
    const uint32_t sb = smem_u32(sm);

    float acc[2][8][4] = {};

    auto load_tiles = [&](int it, int buf) {
        const int k0 = it * 32;
        const uint32_t base = sb + buf * BUF_B;
#pragma unroll
        for (int i = 0; i < 2; i++) {
            const int idx = tid + i * 256;
            const int row = idx >> 2;
            const int ch = idx & 3;
            const uint32_t so = row * PITCH + ch * 16;
            const size_t gA = (size_t)(bm0 + row) * DIMn + k0 + ch * 8;
            const size_t gB = (size_t)(bn0 + row) * DIMn + k0 + ch * 8;
            cp16(base + so, Ah + gA);
            cp16(base + TILE_B + so, Al + gA);
            cp16(base + 2 * TILE_B + so, Bh + gB);
            cp16(base + 3 * TILE_B + so, Bl + gB);
        }
    };

    load_tiles(0, 0);
    CP_COMMIT();

    const int nIter = DIMn / 32;
    for (int it = 0; it < nIter; ++it) {
        if (it + 1 < nIter) {
            load_tiles(it + 1, (it + 1) & 1);
            CP_COMMIT();
            CP_WAIT(1);
        } else {
            CP_WAIT(0);
        }
        __syncthreads();

        const char* base = sm + (it & 1) * BUF_B;
        const char* ahp = base;
        const char* alp = base + TILE_B;
        const char* bhp = base + 2 * TILE_B;
        const char* blp = base + 3 * TILE_B;

#pragma unroll
        for (int k16 = 0; k16 < 32; k16 += 16) {
            uint32_t ah[2][4], al[2][4];
            const int arow = wr * 32 + (lane >> 2);
            const int acol = (k16 + (lane & 3) * 2) * 2;
#pragma unroll
            for (int mt = 0; mt < 2; mt++) {
                const int r0 = (arow + mt * 16) * PITCH + acol;
                const int r1 = r0 + 8 * PITCH;
                ah[mt][0] = *(const uint32_t*)(ahp + r0);
                ah[mt][1] = *(const uint32_t*)(ahp + r1);
                ah[mt][2] = *(const uint32_t*)(ahp + r0 + 16);
                ah[mt][3] = *(const uint32_t*)(ahp + r1 + 16);
                al[mt][0] = *(const uint32_t*)(alp + r0);
                al[mt][1] = *(const uint32_t*)(alp + r1);
                al[mt][2] = *(const uint32_t*)(alp + r0 + 16);
                al[mt][3] = *(const uint32_t*)(alp + r1 + 16);
            }
#pragma unroll
            for (int nt = 0; nt < 8; nt++) {
                const int brow = wc * 64 + nt * 8 + (lane >> 2);
                const int bo = brow * PITCH + acol;
                const uint32_t bh0 = *(const uint32_t*)(bhp + bo);
                const uint32_t bh1 = *(const uint32_t*)(bhp + bo + 16);
                const uint32_t bl0 = *(const uint32_t*)(blp + bo);
                const uint32_t bl1 = *(const uint32_t*)(blp + bo + 16);
#pragma unroll
                for (int mt = 0; mt < 2; mt++) {
                    mma16816(acc[mt][nt], ah[mt], bh0, bh1);
                    mma16816(acc[mt][nt], al[mt], bh0, bh1);
                    mma16816(acc[mt][nt], ah[mt], bl0, bl1);
                }
            }
        }
        __syncthreads();
    }

    // ---- epilogue ----
#pragma unroll
    for (int mt = 0; mt < 2; mt++) {
        const int ra = bm0 + wr * 32 + mt * 16 + (lane >> 2);
        const int rb = ra + 8;
#pragma unroll
        for (int nt = 0; nt < 8; nt++) {
            const int n = bn0 + wc * 64 + nt * 8 + (lane & 3) * 2;
            if (MODE == 0) {
                const int which = n / INNERn;
                const int rem = n - which * INNERn;
                const int h = rem >> 6;
                const int d = rem & 63;
                const int ba = ra >> 10, ia = ra & 1023;
                const int bb = rb >> 10, ib = rb & 1023;
                float v00 = acc[mt][nt][0], v01 = acc[mt][nt][1];
                float v10 = acc[mt][nt][2], v11 = acc[mt][nt][3];
                if (which == 0) {  // Q: fold softmax scale
                    v00 *= SCALEf; v01 *= SCALEf; v10 *= SCALEf; v11 *= SCALEf;
                }
                if (which == 2) {  // V: transposed [bh][d][j]
                    size_t t0 = ((size_t)(ba * Hn + h) * DHn + d) * Nn;
                    size_t t1 = ((size_t)(bb * Hn + h) * DHn + d) * Nn;
                    __nv_bfloat16 h00 = __float2bfloat16(v00);
                    __nv_bfloat16 h01 = __float2bfloat16(v01);
                    __nv_bfloat16 h10 = __float2bfloat16(v10);
                    __nv_bfloat16 h11 = __float2bfloat16(v11);
                    g_vth[t0 + ia] = h00;
                    g_vth[t0 + Nn + ia] = h01;
                    g_vth[t1 + ib] = h10;
                    g_vth[t1 + Nn + ib] = h11;
                    g_vtl[t0 + ia] = __float2bfloat16(v00 - __bfloat162float(h00));
                    g_vtl[t0 + Nn + ia] = __float2bfloat16(v01 - __bfloat162float(h01));
                    g_vtl[t1 + ib] = __float2bfloat16(v10 - __bfloat162float(h10));
                    g_vtl[t1 + ib + Nn] = __float2bfloat16(v11 - __bfloat162float(h11));
                } else {
                    __nv_bfloat16* dh = (which == 0) ? g_qh : g_kh;
                    __nv_bfloat16* dl = (which == 0) ? g_ql : g_kl;
                    uint32_t hi, lo;
                    size_t i0 = ((size_t)(ba * Hn + h) * Nn + ia) * DHn + d;
                    size_t i1 = ((size_t)(bb * Hn + h) * Nn + ib) * DHn + d;
                    split_pair(v00, v01, hi, lo);
                    *reinterpret_cast<uint32_t*>(&dh[i0]) = hi;
                    *reinterpret_cast<uint32_t*>(&dl[i0]) = lo;
                    split_pair(v10, v11, hi, lo);
                    *reinterpret_cast<uint32_t*>(&dh[i1]) = hi;
                    *reinterpret_cast<uint32_t*>(&dl[i1]) = lo;
                }
            } else {
                const float b0 = bias[n], b1 = bias[n + 1];
                float2 v0 = {acc[mt][nt][0] + b0, acc[mt][nt][1] + b1};
                float2 v1 = {acc[mt][nt][2] + b0, acc[mt][nt][3] + b1};
                *(float2*)&C[(size_t)ra * Ncol + n] = v0;
                *(float2*)&C[(size_t)rb * Ncol + n] = v1;
            }
        }
    }
}

// ---------------------------------------------------------------------------
// Tensor-core flash attention, bf16x3 everywhere.
// CTA = (128 q rows, one bh). 8 warps x 16 rows. 16 KV tiles of 64 keys.
// ---------------------------------------------------------------------------
#define OFF_QH 0
#define OFF_QL 16384
#define OFF_KV 32768            // + buf*32768 : KH, KL(+8192), VH(+16384), VL(+24576)
#define OFF_BIAS 98304
#define ATT_SMEM (98304 + 8192) // 106496

__global__ __launch_bounds__(256, 2) void attn_mma(const float* __restrict__ bias_table) {
    extern __shared__ char sm[];
    const uint32_t sb = smem_u32(sm);
    const int tid = threadIdx.x, wid = tid >> 5, lane = tid & 31;
    const int bh = blockIdx.y;
    const int b = bh / Hn, h = bh - b * Hn;
    const int q0 = blockIdx.x * 128;

    const __nv_bfloat16* qhp = g_qh + (size_t)bh * Nn * DHn;
    const __nv_bfloat16* qlp = g_ql + (size_t)bh * Nn * DHn;
    const __nv_bfloat16* khp = g_kh + (size_t)bh * Nn * DHn;
    const __nv_bfloat16* klp = g_kl + (size_t)bh * Nn * DHn;
    const __nv_bfloat16* vhp = g_vth + (size_t)bh * DHn * Nn;
    const __nv_bfloat16* vlp = g_vtl + (size_t)bh * DHn * Nn;

    float* bias_s = (float*)(sm + OFF_BIAS);
    for (int t = tid; t < 2 * Nn - 1; t += 256)
        bias_s[t] = bias_table[h * (2 * Nn - 1) + t];

    // Q tile load: 128 rows x 64 d (hi + lo), swizzled
#pragma unroll
    for (int i = 0; i < 4; i++) {
        const int idx = tid + i * 256;           // 0..1023
        const int row = idx >> 3, ch = idx & 7;
        const uint32_t so = (uint32_t)(row * 128 + ((ch ^ (row & 7)) << 4));
        cp16(sb + OFF_QH + so, qhp + (size_t)(q0 + row) * DHn + ch * 8);
        cp16(sb + OFF_QL + so, qlp + (size_t)(q0 + row) * DHn + ch * 8);
    }

    auto load_kv = [&](int tile, int buf) {
        const uint32_t kb = sb + OFF_KV + buf * 32768;
        const int kv0 = tile * 64;
#pragma unroll
        for (int i = 0; i < 2; i++) {
            const int idx = tid + i * 256;       // 0..511
            const int row = idx >> 3, ch = idx & 7;
            const uint32_t so = (uint32_t)(row * 128 + ((ch ^ (row & 7)) << 4));
            cp16(kb + so,         khp + (size_t)(kv0 + row) * DHn + ch * 8);
            cp16(kb + 8192 + so,  klp + (size_t)(kv0 + row) * DHn + ch * 8);
            cp16(kb + 16384 + so, vhp + (size_t)row * Nn + kv0 + ch * 8);
            cp16(kb + 24576 + so, vlp + (size_t)row * Nn + kv0 + ch * 8);
        }
    };

    load_kv(0, 0);
    CP_COMMIT();

    const int rl = lane >> 2;          // row-in-16 (low half)
    const int cq = (lane & 3) * 4;     // byte offset of k-pair within 32B subrow
    const int gi_lo = q0 + wid * 16 + rl;
    const int gi_hi = gi_lo + 8;

    float m_lo = -1e30f, m_hi = -1e30f, l_lo = 0.f, l_hi = 0.f;
    float acc[8][4] = {};

    for (int t = 0; t < 16; t++) {
        if (t + 1 < 16) {
            load_kv(t + 1, (t + 1) & 1);
            CP_COMMIT();
            CP_WAIT(1);
        } else {
            CP_WAIT(0);
        }
        __syncthreads();

        const uint32_t kb = sb + OFF_KV + (t & 1) * 32768;

        // ---- S = Q @ K^T (bf16x3) ----
        float pc[8][4] = {};
#pragma unroll
        for (int kt = 0; kt < 4; kt++) {
            const int r0 = wid * 16 + rl;
            const int cb = cq + kt * 32;
            const uint32_t o00 = swz128(r0, cb), o01 = swz128(r0, cb + 16);
            const uint32_t o10 = swz128(r0 + 8, cb), o11 = swz128(r0 + 8, cb + 16);
            uint32_t aqh[4], aql[4];
            aqh[0] = lds32(sb + OFF_QH + o00);
            aqh[1] = lds32(sb + OFF_QH + o10);
            aqh[2] = lds32(sb + OFF_QH + o01);
            aqh[3] = lds32(sb + OFF_QH + o11);
            aql[0] = lds32(sb + OFF_QL + o00);
            aql[1] = lds32(sb + OFF_QL + o10);
            aql[2] = lds32(sb + OFF_QL + o01);
            aql[3] = lds32(sb + OFF_QL + o11);
#pragma unroll
            for (int nt = 0; nt < 8; nt++) {
                const int kr = nt * 8 + rl;
                const uint32_t ob0 = swz128(kr, cb), ob1 = swz128(kr, cb + 16);
                const uint32_t bh0 = lds32(kb + ob0);
                const uint32_t bh1 = lds32(kb + ob1);
                const uint32_t bl0 = lds32(kb + 8192 + ob0);
                const uint32_t bl1 = lds32(kb + 8192 + ob1);
                mma16816(pc[nt], aqh, bh0, bh1);
                mma16816(pc[nt], aql, bh0, bh1);
                mma16816(pc[nt], aqh, bl0, bl1);
            }
        }

        // ---- bias + online softmax ----
        float mx_lo = -1e30f, mx_hi = -1e30f;
#pragma unroll
        for (int nt = 0; nt < 8; nt++) {
            const int gj = t * 64 + nt * 8 + (lane & 3) * 2;
            int o0 = gi_lo - gj, o1 = o0 - 1;     // offsets for gj, gj+1
            int o2 = gi_hi - gj, o3 = o2 - 1;
            pc[nt][0] += bias_s[o0 <= 0 ? -o0 : Nn - 1 + o0];
            pc[nt][1] += bias_s[o1 <= 0 ? -o1 : Nn - 1 + o1];
            pc[nt][2] += bias_s[o2 <= 0 ? -o2 : Nn - 1 + o2];
            pc[nt][3] += bias_s[o3 <= 0 ? -o3 : Nn - 1 + o3];
            mx_lo = fmaxf(mx_lo, fmaxf(pc[nt][0], pc[nt][1]));
            mx_hi = fmaxf(mx_hi, fmaxf(pc[nt][2], pc[nt][3]));
        }
        mx_lo = fmaxf(mx_lo, __shfl_xor_sync(0xffffffffu, mx_lo, 1));
        mx_lo = fmaxf(mx_lo, __shfl_xor_sync(0xffffffffu, mx_lo, 2));
        mx_hi = fmaxf(mx_hi, __shfl_xor_sync(0xffffffffu, mx_hi, 1));
        mx_hi = fmaxf(mx_hi, __shfl_xor_sync(0xffffffffu, mx_hi, 2));

        const float nm_lo = fmaxf(m_lo, mx_lo), nm_hi = fmaxf(m_hi, mx_hi);
        const float cr_lo = __expf(m_lo - nm_lo), cr_hi = __expf(m_hi - nm_hi);
        m_lo = nm_lo; m_hi = nm_hi;

        float s_lo = 0.f, s_hi = 0.f;
#pragma unroll
        for (int nt = 0; nt < 8; nt++) {
            pc[nt][0] = __expf(pc[nt][0] - m_lo);
            pc[nt][1] = __expf(pc[nt][1] - m_lo);
            pc[nt][2] = __expf(pc[nt][2] - m_hi);
            pc[nt][3] = __expf(pc[nt][3] - m_hi);
            s_lo += pc[nt][0] + pc[nt][1];
            s_hi += pc[nt][2] + pc[nt][3];
        }
        s_lo += __shfl_xor_sync(0xffffffffu, s_lo, 1);
        s_lo += __shfl_xor_sync(0xffffffffu, s_lo, 2);
        s_hi += __shfl_xor_sync(0xffffffffu, s_hi, 1);
        s_hi += __shfl_xor_sync(0xffffffffu, s_hi, 2);
        l_lo = l_lo * cr_lo + s_lo;
        l_hi = l_hi * cr_hi + s_hi;

#pragma unroll
        for (int nt = 0; nt < 8; nt++) {
            acc[nt][0] *= cr_lo; acc[nt][1] *= cr_lo;
            acc[nt][2] *= cr_hi; acc[nt][3] *= cr_hi;
        }

        // ---- O += P @ V (bf16x3, P stays in registers) ----
#pragma unroll
        for (int kt = 0; kt < 4; kt++) {
            uint32_t ph[4], pl[4];
            split_pair(pc[2 * kt][0], pc[2 * kt][1], ph[0], pl[0]);
            split_pair(pc[2 * kt][2], pc[2 * kt][3], ph[1], pl[1]);
            split_pair(pc[2 * kt + 1][0], pc[2 * kt + 1][1], ph[2], pl[2]);
            split_pair(pc[2 * kt + 1][2], pc[2 * kt + 1][3], ph[3], pl[3]);
            const int cb = cq + kt * 32;
#pragma unroll
            for (int nt = 0; nt < 8; nt++) {
                const int vr = nt * 8 + rl;    // d row of V^T
                const uint32_t o0 = swz128(vr, cb), o1 = swz128(vr, cb + 16);
                const uint32_t vh0 = lds32(kb + 16384 + o0);
                const uint32_t vh1 = lds32(kb + 16384 + o1);
                const uint32_t vl0 = lds32(kb + 24576 + o0);
                const uint32_t vl1 = lds32(kb + 24576 + o1);
                mma16816(acc[nt], ph, vh0, vh1);
                mma16816(acc[nt], pl, vh0, vh1);
                mma16816(acc[nt], ph, vl0, vl1);
            }
        }
        __syncthreads();
    }

    // ---- epilogue: normalize, split, write [b, i, h*64+d] hi/lo ----
    const float inv_lo = 1.f / l_lo, inv_hi = 1.f / l_hi;
#pragma unroll
    for (int nt = 0; nt < 8; nt++) {
        const int d = nt * 8 + (lane & 3) * 2;
        uint32_t hi, lo;
        size_t i0 = (size_t)(b * Nn + gi_lo) * INNERn + h * DHn + d;
        split_pair(acc[nt][0] * inv_lo, acc[nt][1] * inv_lo, hi, lo);
        *reinterpret_cast<uint32_t*>(&g_oh[i0]) = hi;
        *reinterpret_cast<uint32_t*>(&g_ol[i0]) = lo;
        size_t i1 = (size_t)(b * Nn + gi_hi) * INNERn + h * DHn + d;
        split_pair(acc[nt][2] * inv_hi, acc[nt][3] * inv_hi, hi, lo);
        *reinterpret_cast<uint32_t*>(&g_oh[i1]) = hi;
        *reinterpret_cast<uint32_t*>(&g_ol[i1]) = lo;
    }
}

// ---------------------------------------------------------------------------
extern "C" void kernel_launch(void* const* d_in, const int* in_sizes, int n_in,
                              void* d_out, int out_size) {
    const float* x          = (const float*)d_in[0];
    const float* w_qkv      = (const float*)d_in[1];
    const float* bias_table = (const float*)d_in[2];
    const float* w_out      = (const float*)d_in[3];
    const float* b_out      = (const float*)d_in[4];
    float* out = (float*)d_out;

    cudaFuncSetAttribute(attn_mma, cudaFuncAttributeMaxDynamicSharedMemorySize,
                         ATT_SMEM);
    cudaFuncSetAttribute(mma_gemm<0>, cudaFuncAttributeMaxDynamicSharedMemorySize,
                         GEMM_SMEM);
    cudaFuncSetAttribute(mma_gemm<1>, cudaFuncAttributeMaxDynamicSharedMemorySize,
                         GEMM_SMEM);

    __nv_bfloat16 *xh, *xl, *wqh, *wql, *woh, *wol, *oh, *ol;
    cudaGetSymbolAddress((void**)&xh, g_xh);
    cudaGetSymbolAddress((void**)&xl, g_xl);
    cudaGetSymbolAddress((void**)&wqh, g_wqh);
    cudaGetSymbolAddress((void**)&wql, g_wql);
    cudaGetSymbolAddress((void**)&woh, g_woh);
    cudaGetSymbolAddress((void**)&wol, g_wol);
    cudaGetSymbolAddress((void**)&oh, g_oh);
    cudaGetSymbolAddress((void**)&ol, g_ol);

    // 0) splits (x, w_qkv^T, w_out^T)
    split_f32<<<(Mrows * DIMn / 4 + 255) / 256, 256>>>(x, xh, xl, Mrows * DIMn / 4);
    splitT<<<dim3(NCn / 32, DIMn / 32), 256>>>(w_qkv, wqh, wql, DIMn, NCn);
    splitT<<<dim3(INNERn / 32, DIMn / 32), 256>>>(w_out, woh, wol, DIMn, INNERn);

    // 1) QKV projection -> q/k/v bf16 hi/lo (q scaled, v transposed)
    dim3 g1(NCn / 128, Mrows / 128);
    mma_gemm<0><<<g1, 256, GEMM_SMEM>>>(xh, xl, wqh, wql, nullptr, nullptr, NCn);

    // 2) Tensor-core flash attention
    dim3 g2(Nn / 128, Bn * Hn);
    attn_mma<<<g2, 256, ATT_SMEM>>>(bias_table);

    // 3) Output projection + bias
    dim3 g3(INNERn / 128, Mrows / 128);
    mma_gemm<1><<<g3, 256, GEMM_SMEM>>>(oh, ol, woh, wol, out, b_out, INNERn);
}